// round 5
// baseline (speedup 1.0000x reference)
#include <cuda_runtime.h>
#include <cuda_bf16.h>
#include <cstdint>

#define E_EXPERTS 8
#define H_DIM 2048
#define I_DIM 1024
#define T_TOK 16384

// ---------------- device scratch (allocation-free rule) ----------------
__device__ float a_tf32[(size_t)T_TOK * H_DIM];                 // rna-rounded activations [T][H]
__device__ float h_scratch[(size_t)T_TOK * I_DIM];              // swiglu output [T][I]
__device__ float gate_t[(size_t)E_EXPERTS * H_DIM * I_DIM];     // [E][I][H]  (N-major -> K-major)
__device__ float up_t[(size_t)E_EXPERTS * H_DIM * I_DIM];       // [E][I][H]
__device__ float down_t[(size_t)E_EXPERTS * H_DIM * I_DIM];     // [E][H][I]

// ---------------- helpers ----------------
__device__ __forceinline__ float rna_tf32(float x) {
    uint32_t o;
    asm("cvt.rna.tf32.f32 %0, %1;" : "=r"(o) : "f"(x));
    return __uint_as_float(o);
}
__device__ __forceinline__ uint32_t smem_u32(const void* p) {
    return (uint32_t)__cvta_generic_to_shared(p);
}
__device__ __forceinline__ void cp_async16(uint32_t dst, const void* src) {
    asm volatile("cp.async.cg.shared.global [%0], [%1], 16;" :: "r"(dst), "l"(src) : "memory");
}
__device__ __forceinline__ void ldsm_x4(uint32_t* r, uint32_t addr) {
    asm volatile("ldmatrix.sync.aligned.m8n8.x4.shared.b16 {%0,%1,%2,%3}, [%4];"
                 : "=r"(r[0]), "=r"(r[1]), "=r"(r[2]), "=r"(r[3]) : "r"(addr));
}
__device__ __forceinline__ void mma_tf32(float* d, const uint32_t* a, const uint32_t* b) {
    asm volatile(
        "mma.sync.aligned.m16n8k8.row.col.f32.tf32.tf32.f32 "
        "{%0,%1,%2,%3}, {%4,%5,%6,%7}, {%8,%9}, {%0,%1,%2,%3};"
        : "+f"(d[0]), "+f"(d[1]), "+f"(d[2]), "+f"(d[3])
        : "r"(a[0]), "r"(a[1]), "r"(a[2]), "r"(a[3]), "r"(b[0]), "r"(b[1]));
}

// ---------------- prepass kernels ----------------
__global__ void round_kernel(const float4* __restrict__ in, float4* __restrict__ out, int n4) {
    int i = blockIdx.x * blockDim.x + threadIdx.x;
    if (i < n4) {
        float4 v = in[i];
        v.x = rna_tf32(v.x); v.y = rna_tf32(v.y);
        v.z = rna_tf32(v.z); v.w = rna_tf32(v.w);
        out[i] = v;
    }
}

// src: [E][K][N] -> dst: [E][N][K], with rna rounding
__global__ void transpose_rna_kernel(const float* __restrict__ src, float* __restrict__ dst,
                                     int K, int N) {
    __shared__ float t[32][33];
    int e = blockIdx.z;
    const float* s = src + (size_t)e * K * N;
    float* d = dst + (size_t)e * K * N;
    int n0 = blockIdx.x * 32, k0 = blockIdx.y * 32;
    int x = threadIdx.x, y = threadIdx.y;  // 32 x 8
    #pragma unroll
    for (int i = 0; i < 32; i += 8)
        t[y + i][x] = rna_tf32(s[(size_t)(k0 + y + i) * N + n0 + x]);
    __syncthreads();
    #pragma unroll
    for (int i = 0; i < 32; i += 8)
        d[(size_t)(n0 + y + i) * K + k0 + x] = t[x][y + i];
}

// -----------------------------------------------------------------------------
// Grouped GEMM via mma.sync tf32, ldmatrix-fed fragments.
// C[m,n] = sum_k A[m,k] * B[expert(m)][n][k]   (B pre-transposed, K-major)
// CTA 128x128 (per matrix), 256 threads = 8 warps (2 M x 4 N), warp tile 64x32.
// Both A and B smem tiles stored [row][k] with PAD=36 (LDSM conflict-free).
// NB==2: gate+up on shared A frags; epilogue stores rna(silu(g)*u).
// -----------------------------------------------------------------------------
template <int NB, int S>
__global__ __launch_bounds__(256, NB == 1 ? 2 : 1)
void mma_gemm(const float* __restrict__ A, const float* __restrict__ B0,
              const float* __restrict__ B1, const int* __restrict__ gsz,
              float* __restrict__ C, int K, int N) {
    constexpr int BM = 128, BN = 128, BK = 32;
    constexpr int PAD = 36;
    constexpr int T_FL = 128 * PAD;          // floats per tile (A or B): 4608
    constexpr int STAGE = (1 + NB) * T_FL;

    extern __shared__ float sm[];
    __shared__ int bound[E_EXPERTS + 1];

    const int tid = threadIdx.x;
    const int wid = tid >> 5;
    const int lane = tid & 31;
    const int wm = wid & 1;                  // 2 warp-rows of 64
    const int wn = wid >> 1;                 // 4 warp-cols of 32
    const int lr = lane >> 2;
    const int lc = lane & 3;

    // ldmatrix per-lane address components
    const int gi = lane >> 3;                // matrix index 0..3
    const int gr = lane & 7;                 // row within matrix
    // A: matrices (m0,m1)=rows, (m2,m3)=+4 cols
    const int a_row = wm * 64 + ((gi & 1) << 3) + gr;
    const int a_col = (gi >> 1) << 2;
    // B: matrices (m0,m1)=k/k+4 of na, (m2,m3)=k/k+4 of na+1
    const int b_row = wn * 32 + ((gi >> 1) << 3) + gr;
    const int b_col = (gi & 1) << 2;

    if (tid == 0) {
        int acc = 0;
        bound[0] = 0;
        #pragma unroll
        for (int e = 0; e < E_EXPERTS; e++) { acc += gsz[e]; bound[e + 1] = acc; }
    }
    __syncthreads();

    const int m0 = blockIdx.y * BM;
    const int n0 = blockIdx.x * BN;
    const int nch = K / BK;
    const uint32_t sm_u = smem_u32(sm);

    int row = m0;
    while (row < m0 + BM) {
        int e = 0;
        while (bound[e + 1] <= row) e++;
        const int seg_end = bound[e + 1] < m0 + BM ? bound[e + 1] : m0 + BM;
        const float* Bg[2];
        Bg[0] = B0 + (size_t)e * K * N;
        Bg[1] = (NB == 2) ? (B1 + (size_t)e * K * N) : Bg[0];

        float acc[NB][4][4][4];
        #pragma unroll
        for (int j = 0; j < NB; j++)
            #pragma unroll
            for (int ma = 0; ma < 4; ma++)
                #pragma unroll
                for (int na = 0; na < 4; na++)
                    #pragma unroll
                    for (int q = 0; q < 4; q++) acc[j][ma][na][q] = 0.f;

        auto load_stage = [&](int c) {
            int s = c % S;
            float* as = sm + s * STAGE;
            int kc = c * BK;
            // A tile: 128 rows x 32 k  (1024 16B-chunks, 4/thread)
            #pragma unroll
            for (int i = 0; i < 4; i++) {
                int idx = tid + i * 256;
                int r = idx >> 3, kq = (idx & 7) << 2;
                cp_async16(smem_u32(as + r * PAD + kq),
                           A + (size_t)(m0 + r) * K + kc + kq);
            }
            // B tiles: 128 n-rows x 32 k each
            #pragma unroll
            for (int j = 0; j < NB; j++) {
                float* bs = as + (1 + j) * T_FL;
                #pragma unroll
                for (int i = 0; i < 4; i++) {
                    int idx = tid + i * 256;
                    int r = idx >> 3, kq = (idx & 7) << 2;
                    cp_async16(smem_u32(bs + r * PAD + kq),
                               Bg[j] + (size_t)(n0 + r) * K + kc + kq);
                }
            }
            asm volatile("cp.async.commit_group;" ::: "memory");
        };

        #pragma unroll
        for (int c = 0; c < S - 1; c++) load_stage(c);

        for (int c = 0; c < nch; c++) {
            asm volatile("cp.async.wait_group %0;" :: "n"(S - 2));
            __syncthreads();
            if (c + S - 1 < nch) load_stage(c + S - 1);
            else asm volatile("cp.async.commit_group;" ::: "memory");

            const uint32_t as_u = sm_u + (uint32_t)(c % S) * STAGE * 4;
            const uint32_t aA = as_u + (uint32_t)(a_row * PAD + a_col) * 4;
            #pragma unroll
            for (int ks = 0; ks < 4; ks++) {
                const int k0 = ks * 8;
                uint32_t af[4][4];
                #pragma unroll
                for (int ma = 0; ma < 4; ma++)
                    ldsm_x4(af[ma], aA + (uint32_t)(ma * 16 * PAD + k0) * 4);
                #pragma unroll
                for (int j = 0; j < NB; j++) {
                    const uint32_t bB = as_u + (uint32_t)((1 + j) * T_FL) * 4
                                      + (uint32_t)(b_row * PAD + b_col) * 4;
                    #pragma unroll
                    for (int np = 0; np < 2; np++) {
                        uint32_t bq[4];
                        ldsm_x4(bq, bB + (uint32_t)(np * 16 * PAD + k0) * 4);
                        #pragma unroll
                        for (int ma = 0; ma < 4; ma++) {
                            mma_tf32(acc[j][ma][2 * np + 0], af[ma], bq + 0);
                            mma_tf32(acc[j][ma][2 * np + 1], af[ma], bq + 2);
                        }
                    }
                }
            }
        }

        // ---------------- epilogue ----------------
        #pragma unroll
        for (int ma = 0; ma < 4; ma++) {
            int r1 = m0 + wm * 64 + ma * 16 + lr;
            int r2 = r1 + 8;
            bool a1 = (r1 >= row && r1 < seg_end);
            bool a2 = (r2 >= row && r2 < seg_end);
            #pragma unroll
            for (int na = 0; na < 4; na++) {
                int col = n0 + wn * 32 + na * 8 + 2 * lc;
                if (NB == 2) {
                    float g0 = acc[0][ma][na][0], g1 = acc[0][ma][na][1];
                    float g2 = acc[0][ma][na][2], g3 = acc[0][ma][na][3];
                    float u0 = acc[1][ma][na][0], u1 = acc[1][ma][na][1];
                    float u2 = acc[1][ma][na][2], u3 = acc[1][ma][na][3];
                    if (a1) {
                        float2 o;
                        o.x = rna_tf32(g0 / (1.f + __expf(-g0)) * u0);
                        o.y = rna_tf32(g1 / (1.f + __expf(-g1)) * u1);
                        *(float2*)(C + (size_t)r1 * N + col) = o;
                    }
                    if (a2) {
                        float2 o;
                        o.x = rna_tf32(g2 / (1.f + __expf(-g2)) * u2);
                        o.y = rna_tf32(g3 / (1.f + __expf(-g3)) * u3);
                        *(float2*)(C + (size_t)r2 * N + col) = o;
                    }
                } else {
                    if (a1)
                        *(float2*)(C + (size_t)r1 * N + col) =
                            make_float2(acc[0][ma][na][0], acc[0][ma][na][1]);
                    if (a2)
                        *(float2*)(C + (size_t)r2 * N + col) =
                            make_float2(acc[0][ma][na][2], acc[0][ma][na][3]);
                }
            }
        }
        __syncthreads();
        row = seg_end;
    }
}

// ---------------- launch ----------------
extern "C" void kernel_launch(void* const* d_in, const int* in_sizes, int n_in,
                              void* d_out, int out_size) {
    (void)in_sizes; (void)n_in; (void)out_size;
    const float* hidden = (const float*)d_in[0];
    const float* gate_w = (const float*)d_in[1];
    const float* up_w   = (const float*)d_in[2];
    const float* down_w = (const float*)d_in[3];
    const int*   gs     = (const int*)d_in[4];
    float* out = (float*)d_out;

    float *aP, *hP, *gP, *uP, *dP;
    cudaGetSymbolAddress((void**)&aP, a_tf32);
    cudaGetSymbolAddress((void**)&hP, h_scratch);
    cudaGetSymbolAddress((void**)&gP, gate_t);
    cudaGetSymbolAddress((void**)&uP, up_t);
    cudaGetSymbolAddress((void**)&dP, down_t);

    // smem: fused S=3: 3*3*4608*4 = 165888 B; down S=3: 3*2*4608*4 = 110592 B
    constexpr int SMEM_FUSED = 3 * 3 * 4608 * 4;
    constexpr int SMEM_DOWN  = 3 * 2 * 4608 * 4;
    cudaFuncSetAttribute((const void*)mma_gemm<2, 3>,
                         cudaFuncAttributeMaxDynamicSharedMemorySize, SMEM_FUSED);
    cudaFuncSetAttribute((const void*)mma_gemm<1, 3>,
                         cudaFuncAttributeMaxDynamicSharedMemorySize, SMEM_DOWN);

    // prepass: round activations; transpose+round weights to [E][N][K]
    int nA4 = (int)((size_t)T_TOK * H_DIM / 4);
    round_kernel<<<(nA4 + 255) / 256, 256>>>((const float4*)hidden, (float4*)aP, nA4);
    transpose_rna_kernel<<<dim3(I_DIM / 32, H_DIM / 32, E_EXPERTS), dim3(32, 8)>>>(gate_w, gP, H_DIM, I_DIM);
    transpose_rna_kernel<<<dim3(I_DIM / 32, H_DIM / 32, E_EXPERTS), dim3(32, 8)>>>(up_w,   uP, H_DIM, I_DIM);
    transpose_rna_kernel<<<dim3(H_DIM / 32, I_DIM / 32, E_EXPERTS), dim3(32, 8)>>>(down_w, dP, I_DIM, H_DIM);

    // fused gate/up + SwiGLU -> h   (A=[T,H], B=[I,H] K-major)
    mma_gemm<2, 3><<<dim3(I_DIM / 128, T_TOK / 128), 256, SMEM_FUSED>>>(
        aP, gP, uP, gs, hP, H_DIM, I_DIM);
    // down projection -> out        (A=[T,I], B=[H,I] K-major)
    mma_gemm<1, 3><<<dim3(H_DIM / 128, T_TOK / 128), 256, SMEM_DOWN>>>(
        hP, dP, nullptr, gs, out, I_DIM, H_DIM);
}

// round 6
// speedup vs baseline: 1.3513x; 1.3513x over previous
#include <cuda_runtime.h>
#include <cuda_bf16.h>
#include <cstdint>

#define E_EXPERTS 8
#define H_DIM 2048
#define I_DIM 1024
#define T_TOK 16384

// ---------------- device scratch (allocation-free rule) ----------------
__device__ float u_scratch[(size_t)T_TOK * I_DIM];   // up-proj result
__device__ float h_scratch[(size_t)T_TOK * I_DIM];   // swiglu output (tf32-rounded)

// ---------------- helpers ----------------
__device__ __forceinline__ float rna_tf32(float x) {
    uint32_t o;
    asm("cvt.rna.tf32.f32 %0, %1;" : "=r"(o) : "f"(x));
    return __uint_as_float(o);
}
__device__ __forceinline__ uint32_t rna_tf32_u(float x) {
    uint32_t o;
    asm("cvt.rna.tf32.f32 %0, %1;" : "=r"(o) : "f"(x));
    return o;
}
__device__ __forceinline__ uint32_t smem_u32(const void* p) {
    return (uint32_t)__cvta_generic_to_shared(p);
}
__device__ __forceinline__ void cp_async16(uint32_t dst, const void* src) {
    asm volatile("cp.async.cg.shared.global [%0], [%1], 16;" :: "r"(dst), "l"(src) : "memory");
}
__device__ __forceinline__ void mma_tf32(float* d, const uint32_t* a, const uint32_t* b) {
    asm volatile(
        "mma.sync.aligned.m16n8k8.row.col.f32.tf32.tf32.f32 "
        "{%0,%1,%2,%3}, {%4,%5,%6,%7}, {%8,%9}, {%0,%1,%2,%3};"
        : "+f"(d[0]), "+f"(d[1]), "+f"(d[2]), "+f"(d[3])
        : "r"(a[0]), "r"(a[1]), "r"(a[2]), "r"(a[3]), "r"(b[0]), "r"(b[1]));
}

// -----------------------------------------------------------------------------
// Grouped GEMM via mma.sync tf32 (round-4 proven structure, NB=1, 2 CTA/SM).
// C[m,n] = sum_k rna(A[m,k]) * rna(B[expert(m)][k,n])   (cvt in-loop, no prepass)
// CTA 128x128, 256 threads = 8 warps (2 M x 4 N), warp tile 64x32, BK=32, S=3.
// CVT_A: apply rna to A fragments (0 when A is already tf32-rounded, e.g. h).
// EPI==1: epilogue loads u from aux and stores rna(silu(acc)*u) (SwiGLU).
// -----------------------------------------------------------------------------
template <int CVT_A, int EPI>
__global__ __launch_bounds__(256, 2)
void mma_gemm(const float* __restrict__ A, const float* __restrict__ B0,
              const float* __restrict__ aux, const int* __restrict__ gsz,
              float* __restrict__ C, int K, int N) {
    constexpr int BM = 128, BN = 128, BK = 32, S = 3;
    constexpr int APAD = 36;
    constexpr int BPAD = BN + 8;            // 136
    constexpr int A_FL = BM * APAD;         // 4608
    constexpr int B_FL = BK * BPAD;         // 4352
    constexpr int STAGE = A_FL + B_FL;      // 8960 floats

    extern __shared__ float sm[];
    __shared__ int bound[E_EXPERTS + 1];

    const int tid = threadIdx.x;
    const int wid = tid >> 5;
    const int lane = tid & 31;
    const int wm = wid & 1;                 // 2 warp-rows of 64
    const int wn = wid >> 1;                // 4 warp-cols of 32
    const int lr = lane >> 2;               // 0..7
    const int lc = lane & 3;                // 0..3

    if (tid == 0) {
        int acc = 0;
        bound[0] = 0;
        #pragma unroll
        for (int e = 0; e < E_EXPERTS; e++) { acc += gsz[e]; bound[e + 1] = acc; }
    }
    __syncthreads();

    const int m0 = blockIdx.y * BM;
    const int n0 = blockIdx.x * BN;
    const int nch = K / BK;

    int row = m0;
    while (row < m0 + BM) {
        int e = 0;
        while (bound[e + 1] <= row) e++;
        const int seg_end = bound[e + 1] < m0 + BM ? bound[e + 1] : m0 + BM;
        const float* Be = B0 + (size_t)e * K * N;

        float acc[4][4][4];                 // [ma][na][quad]
        #pragma unroll
        for (int ma = 0; ma < 4; ma++)
            #pragma unroll
            for (int na = 0; na < 4; na++)
                #pragma unroll
                for (int q = 0; q < 4; q++) acc[ma][na][q] = 0.f;

        auto load_stage = [&](int c) {
            int s = c % S;
            float* as = sm + s * STAGE;
            int kc = c * BK;
            #pragma unroll
            for (int i = 0; i < 4; i++) {
                int idx = tid + i * 256;
                int m = idx >> 3, kq = (idx & 7) << 2;
                cp_async16(smem_u32(as + m * APAD + kq),
                           A + (size_t)(m0 + m) * K + kc + kq);
            }
            float* bs = as + A_FL;
            #pragma unroll
            for (int i = 0; i < 4; i++) {
                int idx = tid + i * 256;
                int kr = idx >> 5, nq = (idx & 31) << 2;
                cp_async16(smem_u32(bs + kr * BPAD + nq),
                           Be + (size_t)(kc + kr) * N + n0 + nq);
            }
            asm volatile("cp.async.commit_group;" ::: "memory");
        };

        #pragma unroll
        for (int c = 0; c < S - 1; c++) load_stage(c);

        for (int c = 0; c < nch; c++) {
            asm volatile("cp.async.wait_group %0;" :: "n"(S - 2));
            __syncthreads();
            if (c + S - 1 < nch) load_stage(c + S - 1);
            else asm volatile("cp.async.commit_group;" ::: "memory");

            const float* as = sm + (c % S) * STAGE;
            #pragma unroll
            for (int ks = 0; ks < 4; ks++) {
                const int k0 = ks * 8;
                uint32_t af[4][4];
                #pragma unroll
                for (int ma = 0; ma < 4; ma++) {
                    int rb = wm * 64 + ma * 16 + lr;
                    const float* ar = as + (size_t)rb * APAD + k0 + lc;
                    if (CVT_A) {
                        af[ma][0] = rna_tf32_u(ar[0]);
                        af[ma][1] = rna_tf32_u(ar[8 * APAD]);
                        af[ma][2] = rna_tf32_u(ar[4]);
                        af[ma][3] = rna_tf32_u(ar[8 * APAD + 4]);
                    } else {
                        af[ma][0] = __float_as_uint(ar[0]);
                        af[ma][1] = __float_as_uint(ar[8 * APAD]);
                        af[ma][2] = __float_as_uint(ar[4]);
                        af[ma][3] = __float_as_uint(ar[8 * APAD + 4]);
                    }
                }
                const float* bs = as + A_FL;
                #pragma unroll
                for (int na = 0; na < 4; na++) {
                    int cb = wn * 32 + na * 8 + lr;
                    uint32_t bf[2];
                    bf[0] = rna_tf32_u(bs[(size_t)(k0 + lc) * BPAD + cb]);
                    bf[1] = rna_tf32_u(bs[(size_t)(k0 + lc + 4) * BPAD + cb]);
                    #pragma unroll
                    for (int ma = 0; ma < 4; ma++)
                        mma_tf32(acc[ma][na], af[ma], bf);
                }
            }
        }

        // ---------------- epilogue ----------------
        #pragma unroll
        for (int ma = 0; ma < 4; ma++) {
            int r1 = m0 + wm * 64 + ma * 16 + lr;
            int r2 = r1 + 8;
            bool a1 = (r1 >= row && r1 < seg_end);
            bool a2 = (r2 >= row && r2 < seg_end);
            #pragma unroll
            for (int na = 0; na < 4; na++) {
                int col = n0 + wn * 32 + na * 8 + 2 * lc;
                if (EPI == 1) {
                    if (a1) {
                        float2 uv = *(const float2*)(aux + (size_t)r1 * N + col);
                        float g0 = acc[ma][na][0], g1 = acc[ma][na][1];
                        float2 o;
                        o.x = rna_tf32(g0 / (1.f + __expf(-g0)) * uv.x);
                        o.y = rna_tf32(g1 / (1.f + __expf(-g1)) * uv.y);
                        *(float2*)(C + (size_t)r1 * N + col) = o;
                    }
                    if (a2) {
                        float2 uv = *(const float2*)(aux + (size_t)r2 * N + col);
                        float g2 = acc[ma][na][2], g3 = acc[ma][na][3];
                        float2 o;
                        o.x = rna_tf32(g2 / (1.f + __expf(-g2)) * uv.x);
                        o.y = rna_tf32(g3 / (1.f + __expf(-g3)) * uv.y);
                        *(float2*)(C + (size_t)r2 * N + col) = o;
                    }
                } else {
                    if (a1)
                        *(float2*)(C + (size_t)r1 * N + col) =
                            make_float2(acc[ma][na][0], acc[ma][na][1]);
                    if (a2)
                        *(float2*)(C + (size_t)r2 * N + col) =
                            make_float2(acc[ma][na][2], acc[ma][na][3]);
                }
            }
        }
        __syncthreads();   // protect smem ring across segments / tail cp.asyncs
        row = seg_end;
    }
}

// ---------------- launch ----------------
extern "C" void kernel_launch(void* const* d_in, const int* in_sizes, int n_in,
                              void* d_out, int out_size) {
    (void)in_sizes; (void)n_in; (void)out_size;
    const float* hidden = (const float*)d_in[0];
    const float* gate_w = (const float*)d_in[1];
    const float* up_w   = (const float*)d_in[2];
    const float* down_w = (const float*)d_in[3];
    const int*   gs     = (const int*)d_in[4];
    float* out = (float*)d_out;

    float *uP, *hP;
    cudaGetSymbolAddress((void**)&uP, u_scratch);
    cudaGetSymbolAddress((void**)&hP, h_scratch);

    constexpr int SMEM = 3 * (4608 + 4352) * 4;   // 107,520 B -> 2 CTA/SM
    cudaFuncSetAttribute((const void*)mma_gemm<1, 0>,
                         cudaFuncAttributeMaxDynamicSharedMemorySize, SMEM);
    cudaFuncSetAttribute((const void*)mma_gemm<1, 1>,
                         cudaFuncAttributeMaxDynamicSharedMemorySize, SMEM);
    cudaFuncSetAttribute((const void*)mma_gemm<0, 0>,
                         cudaFuncAttributeMaxDynamicSharedMemorySize, SMEM);

    // 1) up-projection: u = hidden @ up_w         (A=[T,H], B=[H,I])
    mma_gemm<1, 0><<<dim3(I_DIM / 128, T_TOK / 128), 256, SMEM>>>(
        hidden, up_w, nullptr, gs, uP, H_DIM, I_DIM);
    // 2) gate + SwiGLU: h = rna(silu(hidden @ gate_w) * u)
    mma_gemm<1, 1><<<dim3(I_DIM / 128, T_TOK / 128), 256, SMEM>>>(
        hidden, gate_w, uP, gs, hP, H_DIM, I_DIM);
    // 3) down-projection: out = h @ down_w        (A=[T,I], B=[I,H])
    mma_gemm<0, 0><<<dim3(H_DIM / 128, T_TOK / 128), 256, SMEM>>>(
        hP, down_w, nullptr, gs, out, I_DIM, H_DIM);
}

// round 7
// speedup vs baseline: 1.4729x; 1.0899x over previous
#include <cuda_runtime.h>
#include <cuda_bf16.h>
#include <cstdint>

#define E_EXPERTS 8
#define H_DIM 2048
#define I_DIM 1024
#define T_TOK 16384

// ---------------- device scratch (allocation-free rule) ----------------
__device__ float a_r[(size_t)T_TOK * H_DIM];                  // rna-rounded activations
__device__ float u_scratch[(size_t)T_TOK * I_DIM];            // up-proj result
__device__ float h_scratch[(size_t)T_TOK * I_DIM];            // swiglu output (rounded)
__device__ float gate_r[(size_t)E_EXPERTS * H_DIM * I_DIM];   // rna-rounded weights [E][K][N]
__device__ float up_r[(size_t)E_EXPERTS * H_DIM * I_DIM];
__device__ float down_r[(size_t)E_EXPERTS * H_DIM * I_DIM];

// ---------------- helpers ----------------
__device__ __forceinline__ float rna_tf32(float x) {
    uint32_t o;
    asm("cvt.rna.tf32.f32 %0, %1;" : "=r"(o) : "f"(x));
    return __uint_as_float(o);
}
__device__ __forceinline__ uint32_t smem_u32(const void* p) {
    return (uint32_t)__cvta_generic_to_shared(p);
}
__device__ __forceinline__ void cp_async16(uint32_t dst, const void* src) {
    asm volatile("cp.async.cg.shared.global [%0], [%1], 16;" :: "r"(dst), "l"(src) : "memory");
}
__device__ __forceinline__ void ldsm_x4(uint32_t* r, uint32_t addr) {
    asm volatile("ldmatrix.sync.aligned.m8n8.x4.shared.b16 {%0,%1,%2,%3}, [%4];"
                 : "=r"(r[0]), "=r"(r[1]), "=r"(r[2]), "=r"(r[3]) : "r"(addr));
}
__device__ __forceinline__ void mma_tf32(float* d, const uint32_t* a, const uint32_t* b) {
    asm volatile(
        "mma.sync.aligned.m16n8k8.row.col.f32.tf32.tf32.f32 "
        "{%0,%1,%2,%3}, {%4,%5,%6,%7}, {%8,%9}, {%0,%1,%2,%3};"
        : "+f"(d[0]), "+f"(d[1]), "+f"(d[2]), "+f"(d[3])
        : "r"(a[0]), "r"(a[1]), "r"(a[2]), "r"(a[3]), "r"(b[0]), "r"(b[1]));
}

// ---------------- prepass: rna-round (elementwise) ----------------
__global__ void round_kernel(const float4* __restrict__ in, float4* __restrict__ out, int n4) {
    int i = blockIdx.x * blockDim.x + threadIdx.x;
    if (i < n4) {
        float4 v = in[i];
        v.x = rna_tf32(v.x); v.y = rna_tf32(v.y);
        v.z = rna_tf32(v.z); v.w = rna_tf32(v.w);
        out[i] = v;
    }
}

// -----------------------------------------------------------------------------
// Grouped GEMM via mma.sync tf32; all operands pre-rounded (no cvt in loop).
// C[m,n] = sum_k A[m,k] * B[expert(m)][k,n]
// CTA 128x128, 256 threads = 8 warps (2 M x 4 N), warp tile 64x32, BK=32, S=3,
// 2 CTA/SM. A fragments via ldmatrix.x4 (conflict-free @ PAD=36), B scalar LDS
// from [k][n] layout. EPI==1: epilogue loads u from aux, stores rna(silu(g)*u).
// -----------------------------------------------------------------------------
template <int EPI>
__global__ __launch_bounds__(256, 2)
void mma_gemm(const float* __restrict__ A, const float* __restrict__ B0,
              const float* __restrict__ aux, const int* __restrict__ gsz,
              float* __restrict__ C, int K, int N) {
    constexpr int BM = 128, BN = 128, BK = 32, S = 3;
    constexpr int APAD = 36;
    constexpr int BPAD = BN + 8;            // 136
    constexpr int A_FL = BM * APAD;         // 4608
    constexpr int B_FL = BK * BPAD;         // 4352
    constexpr int STAGE = A_FL + B_FL;      // 8960 floats

    extern __shared__ float sm[];
    __shared__ int bound[E_EXPERTS + 1];

    const int tid = threadIdx.x;
    const int wid = tid >> 5;
    const int lane = tid & 31;
    const int wm = wid & 1;                 // 2 warp-rows of 64
    const int wn = wid >> 1;                // 4 warp-cols of 32
    const int lr = lane >> 2;               // 0..7
    const int lc = lane & 3;                // 0..3

    // ldmatrix A lane-address: matrix gi: (gi&1)->row +8, (gi>>1)->col +4
    const int gi = lane >> 3;
    const int gr = lane & 7;
    const int a_row = wm * 64 + ((gi & 1) << 3) + gr;
    const int a_col = (gi >> 1) << 2;

    if (tid == 0) {
        int acc = 0;
        bound[0] = 0;
        #pragma unroll
        for (int e = 0; e < E_EXPERTS; e++) { acc += gsz[e]; bound[e + 1] = acc; }
    }
    __syncthreads();

    const int m0 = blockIdx.y * BM;
    const int n0 = blockIdx.x * BN;
    const int nch = K / BK;
    const uint32_t sm_u = smem_u32(sm);

    int row = m0;
    while (row < m0 + BM) {
        int e = 0;
        while (bound[e + 1] <= row) e++;
        const int seg_end = bound[e + 1] < m0 + BM ? bound[e + 1] : m0 + BM;
        const float* Be = B0 + (size_t)e * K * N;

        float acc[4][4][4];                 // [ma][na][quad]
        #pragma unroll
        for (int ma = 0; ma < 4; ma++)
            #pragma unroll
            for (int na = 0; na < 4; na++)
                #pragma unroll
                for (int q = 0; q < 4; q++) acc[ma][na][q] = 0.f;

        auto load_stage = [&](int c) {
            int s = c % S;
            float* as = sm + s * STAGE;
            int kc = c * BK;
            #pragma unroll
            for (int i = 0; i < 4; i++) {
                int idx = tid + i * 256;
                int m = idx >> 3, kq = (idx & 7) << 2;
                cp_async16(smem_u32(as + m * APAD + kq),
                           A + (size_t)(m0 + m) * K + kc + kq);
            }
            float* bs = as + A_FL;
            #pragma unroll
            for (int i = 0; i < 4; i++) {
                int idx = tid + i * 256;
                int kr = idx >> 5, nq = (idx & 31) << 2;
                cp_async16(smem_u32(bs + kr * BPAD + nq),
                           Be + (size_t)(kc + kr) * N + n0 + nq);
            }
            asm volatile("cp.async.commit_group;" ::: "memory");
        };

        #pragma unroll
        for (int c = 0; c < S - 1; c++) load_stage(c);

        for (int c = 0; c < nch; c++) {
            asm volatile("cp.async.wait_group %0;" :: "n"(S - 2));
            __syncthreads();
            if (c + S - 1 < nch) load_stage(c + S - 1);
            else asm volatile("cp.async.commit_group;" ::: "memory");

            const uint32_t as_u = sm_u + (uint32_t)((c % S) * STAGE) * 4u;
            const float* bs = sm + (c % S) * STAGE + A_FL;
            const uint32_t aA = as_u + (uint32_t)(a_row * APAD + a_col) * 4u;
            #pragma unroll
            for (int ks = 0; ks < 4; ks++) {
                const int k0 = ks * 8;
                uint32_t af[4][4];
                #pragma unroll
                for (int ma = 0; ma < 4; ma++)
                    ldsm_x4(af[ma], aA + (uint32_t)(ma * 16 * APAD + k0) * 4u);
                #pragma unroll
                for (int na = 0; na < 4; na++) {
                    int cb = wn * 32 + na * 8 + lr;
                    uint32_t bf[2];
                    bf[0] = __float_as_uint(bs[(size_t)(k0 + lc) * BPAD + cb]);
                    bf[1] = __float_as_uint(bs[(size_t)(k0 + lc + 4) * BPAD + cb]);
                    #pragma unroll
                    for (int ma = 0; ma < 4; ma++)
                        mma_tf32(acc[ma][na], af[ma], bf);
                }
            }
        }

        // ---------------- epilogue ----------------
        #pragma unroll
        for (int ma = 0; ma < 4; ma++) {
            int r1 = m0 + wm * 64 + ma * 16 + lr;
            int r2 = r1 + 8;
            bool a1 = (r1 >= row && r1 < seg_end);
            bool a2 = (r2 >= row && r2 < seg_end);
            #pragma unroll
            for (int na = 0; na < 4; na++) {
                int col = n0 + wn * 32 + na * 8 + 2 * lc;
                if (EPI == 1) {
                    if (a1) {
                        float2 uv = *(const float2*)(aux + (size_t)r1 * N + col);
                        float g0 = acc[ma][na][0], g1 = acc[ma][na][1];
                        float2 o;
                        o.x = rna_tf32(g0 / (1.f + __expf(-g0)) * uv.x);
                        o.y = rna_tf32(g1 / (1.f + __expf(-g1)) * uv.y);
                        *(float2*)(C + (size_t)r1 * N + col) = o;
                    }
                    if (a2) {
                        float2 uv = *(const float2*)(aux + (size_t)r2 * N + col);
                        float g2 = acc[ma][na][2], g3 = acc[ma][na][3];
                        float2 o;
                        o.x = rna_tf32(g2 / (1.f + __expf(-g2)) * uv.x);
                        o.y = rna_tf32(g3 / (1.f + __expf(-g3)) * uv.y);
                        *(float2*)(C + (size_t)r2 * N + col) = o;
                    }
                } else {
                    if (a1)
                        *(float2*)(C + (size_t)r1 * N + col) =
                            make_float2(acc[ma][na][0], acc[ma][na][1]);
                    if (a2)
                        *(float2*)(C + (size_t)r2 * N + col) =
                            make_float2(acc[ma][na][2], acc[ma][na][3]);
                }
            }
        }
        __syncthreads();   // protect smem ring across segments / tail cp.asyncs
        row = seg_end;
    }
}

// ---------------- launch ----------------
extern "C" void kernel_launch(void* const* d_in, const int* in_sizes, int n_in,
                              void* d_out, int out_size) {
    (void)in_sizes; (void)n_in; (void)out_size;
    const float* hidden = (const float*)d_in[0];
    const float* gate_w = (const float*)d_in[1];
    const float* up_w   = (const float*)d_in[2];
    const float* down_w = (const float*)d_in[3];
    const int*   gs     = (const int*)d_in[4];
    float* out = (float*)d_out;

    float *aP, *uP, *hP, *gP, *upP, *dP;
    cudaGetSymbolAddress((void**)&aP, a_r);
    cudaGetSymbolAddress((void**)&uP, u_scratch);
    cudaGetSymbolAddress((void**)&hP, h_scratch);
    cudaGetSymbolAddress((void**)&gP, gate_r);
    cudaGetSymbolAddress((void**)&upP, up_r);
    cudaGetSymbolAddress((void**)&dP, down_r);

    constexpr int SMEM = 3 * (4608 + 4352) * 4;   // 107,520 B -> 2 CTA/SM
    cudaFuncSetAttribute((const void*)mma_gemm<0>,
                         cudaFuncAttributeMaxDynamicSharedMemorySize, SMEM);
    cudaFuncSetAttribute((const void*)mma_gemm<1>,
                         cudaFuncAttributeMaxDynamicSharedMemorySize, SMEM);

    // prepass: rna-round activations and all weights (no cvt in mainloops)
    int nA4 = (int)((size_t)T_TOK * H_DIM / 4);
    int nW4 = (int)((size_t)E_EXPERTS * H_DIM * I_DIM / 4);
    round_kernel<<<(nA4 + 255) / 256, 256>>>((const float4*)hidden, (float4*)aP, nA4);
    round_kernel<<<(nW4 + 255) / 256, 256>>>((const float4*)gate_w, (float4*)gP, nW4);
    round_kernel<<<(nW4 + 255) / 256, 256>>>((const float4*)up_w,   (float4*)upP, nW4);
    round_kernel<<<(nW4 + 255) / 256, 256>>>((const float4*)down_w, (float4*)dP, nW4);

    // 1) up-projection: u = a @ up_w              (A=[T,H], B=[H,I])
    mma_gemm<0><<<dim3(I_DIM / 128, T_TOK / 128), 256, SMEM>>>(
        aP, upP, nullptr, gs, uP, H_DIM, I_DIM);
    // 2) gate + SwiGLU: h = rna(silu(a @ gate_w) * u)
    mma_gemm<1><<<dim3(I_DIM / 128, T_TOK / 128), 256, SMEM>>>(
        aP, gP, uP, gs, hP, H_DIM, I_DIM);
    // 3) down-projection: out = h @ down_w        (A=[T,I], B=[I,H])
    mma_gemm<0><<<dim3(H_DIM / 128, T_TOK / 128), 256, SMEM>>>(
        hP, dP, nullptr, gs, out, I_DIM, H_DIM);
}